// round 3
// baseline (speedup 1.0000x reference)
#include <cuda_runtime.h>

constexpr int Wd = 1024, Hd = 1024;
constexpr long HW = (long)Wd * Hd;
constexpr int CIN = 18;
constexpr float L2E = 1.4426950408889634f;

using u64 = unsigned long long;

__device__ __forceinline__ u64 pack2(float lo, float hi) {
    u64 r; asm("mov.b64 %0,{%1,%2};" : "=l"(r) : "f"(lo), "f"(hi)); return r;
}
__device__ __forceinline__ void unpack2(u64 v, float& lo, float& hi) {
    asm("mov.b64 {%0,%1},%2;" : "=f"(lo), "=f"(hi) : "l"(v));
}
__device__ __forceinline__ u64 fma2(u64 a, u64 b, u64 c) {
    u64 d; asm("fma.rn.f32x2 %0,%1,%2,%3;" : "=l"(d) : "l"(a), "l"(b), "l"(c)); return d;
}
__device__ __forceinline__ u64 add2(u64 a, u64 b) {
    u64 d; asm("add.rn.f32x2 %0,%1,%2;" : "=l"(d) : "l"(a), "l"(b)); return d;
}
__device__ __forceinline__ float ex2(float x) {
    float r; asm("ex2.approx.f32 %0,%1;" : "=f"(r) : "f"(x)); return r;
}
__device__ __forceinline__ u64 bcast2(float x) {
    unsigned u = __float_as_uint(x); return ((u64)u << 32) | u;
}

// ---------------------------------------------------------------------------
// Interior: 4 px/thread, f32x2 math, Horner form (no explicit squares),
// per-pixel range params manually spilled to per-thread SMEM slots.
// ---------------------------------------------------------------------------
__device__ __forceinline__ void interior_path(const float* __restrict__ in,
                                              float* __restrict__ out,
                                              u64 (*s_rp)[128], u64 (*s_mf)[128],
                                              int bx, int byi, int bz)
{
    const int t   = threadIdx.y * 32 + threadIdx.x;      // 0..127
    const int gxg = bx * 32 + threadIdx.x;
    const int x0  = 4 + gxg * 4;
    const int y   = 3 + byi * 4 + threadIdx.y;
    if (gxg > 253 || y > 1020) return;

    const float* base = in + (long)bz * CIN * HW;
    const long ctr = (long)y * Wd + x0;

    u64 K2[2], sxl2[2], syl2[2];
    {
        float Ks[4] = {0.f, 0.f, 0.f, 0.f};
        #pragma unroll
        for (int c = 0; c < 8; ++c) {
            float4 fv = *(const float4*)(base + c * HW + ctr);
            float4 pv = *(const float4*)(base + (8 + c) * HW + ctr);
            const float f4[4] = {fv.x, fv.y, fv.z, fv.w};
            const float p4[4] = {pv.x, pv.y, pv.z, pv.w};
            float rs[4], ms[4];
            #pragma unroll
            for (int p = 0; p < 4; ++p) {
                float r = -(p4[p] * p4[p]) * L2E;        // log2(e) folded in
                rs[p] = r;
                ms[p] = -2.f * r * f4[p];
                Ks[p] = fmaf(r * f4[p], f4[p], Ks[p]);
            }
            s_rp[c * 2 + 0][t] = pack2(rs[0], rs[1]);
            s_rp[c * 2 + 1][t] = pack2(rs[2], rs[3]);
            s_mf[c * 2 + 0][t] = pack2(ms[0], ms[1]);
            s_mf[c * 2 + 1][t] = pack2(ms[2], ms[3]);
        }
        K2[0] = pack2(Ks[0], Ks[1]); K2[1] = pack2(Ks[2], Ks[3]);
        float4 sv = *(const float4*)(base + 16 * HW + ctr);
        float4 tv = *(const float4*)(base + 17 * HW + ctr);
        sxl2[0] = pack2(-(sv.x*sv.x)*L2E, -(sv.y*sv.y)*L2E);
        sxl2[1] = pack2(-(sv.z*sv.z)*L2E, -(sv.w*sv.w)*L2E);
        syl2[0] = pack2(-(tv.x*tv.x)*L2E, -(tv.y*tv.y)*L2E);
        syl2[1] = pack2(-(tv.z*tv.z)*L2E, -(tv.w*tv.w)*L2E);
    }

    // Per-channel row base pointers: row i offsets (i*4KB) fold into LDG imm.
    const float* pc[8];
    #pragma unroll
    for (int c = 0; c < 8; ++c)
        pc[c] = base + c * HW + (long)(y - 3) * Wd + (x0 - 4);

    u64 acc2[3][2] = {}, ws2[2] = {};

    #pragma unroll 1       // keep body inside I$ L1.5
    for (int i = 0; i < 7; ++i) {
        const u64 dyb = bcast2((float)((i - 3) * (i - 3)));

        u64 s2[7][2];
        {
            const u64 kd0 = fma2(syl2[0], dyb, K2[0]);
            const u64 kd1 = fma2(syl2[1], dyb, K2[1]);
            #pragma unroll
            for (int j = 0; j < 7; ++j) { s2[j][0] = kd0; s2[j][1] = kd1; }
        }

        #pragma unroll
        for (int c = 0; c < 8; ++c) {
            const u64 rp0 = s_rp[c * 2 + 0][t], rp1 = s_rp[c * 2 + 1][t];
            const u64 mf0 = s_mf[c * 2 + 0][t], mf1 = s_mf[c * 2 + 1][t];
            const float* r0 = pc[c] + i * Wd;
            float4 v0 = *(const float4*)(r0);
            float4 v1 = *(const float4*)(r0 + 4);
            float4 v2 = *(const float4*)(r0 + 8);
            const float nv[12] = {v0.x, v0.y, v0.z, v0.w,
                                  v1.x, v1.y, v1.z, v1.w,
                                  v2.x, v2.y, v2.z, v2.w};
            u64 pv[9];
            #pragma unroll
            for (int k = 0; k < 9; ++k) pv[k] = pack2(nv[k + 1], nv[k + 2]);

            #pragma unroll
            for (int j = 0; j < 7; ++j) {
                // s += fn * (rp*fn + mf)   (Horner: no explicit square)
                s2[j][0] = fma2(pv[j],     fma2(rp0, pv[j],     mf0), s2[j][0]);
                s2[j][1] = fma2(pv[j + 2], fma2(rp1, pv[j + 2], mf1), s2[j][1]);
            }
        }

        // Weights first (s2 dies progressively into w2a)
        u64 w2a[7][2];
        #pragma unroll
        for (int j = 0; j < 7; ++j) {
            const u64 dxb = bcast2((float)((j - 3) * (j - 3)));
            #pragma unroll
            for (int pp = 0; pp < 2; ++pp) {
                u64 lw2 = fma2(sxl2[pp], dxb, s2[j][pp]);
                float a, b; unpack2(lw2, a, b);
                u64 w2 = pack2(ex2(a), ex2(b));
                w2a[j][pp] = w2;
                ws2[pp] = add2(ws2[pp], w2);
            }
        }

        // Accumulate output channels (reload rows: guaranteed L1 hits)
        #pragma unroll
        for (int c = 0; c < 3; ++c) {
            const float* r0 = pc[c] + i * Wd;
            float4 v0 = *(const float4*)(r0);
            float4 v1 = *(const float4*)(r0 + 4);
            float4 v2 = *(const float4*)(r0 + 8);
            const float nv[12] = {v0.x, v0.y, v0.z, v0.w,
                                  v1.x, v1.y, v1.z, v1.w,
                                  v2.x, v2.y, v2.z, v2.w};
            #pragma unroll
            for (int j = 0; j < 7; ++j) {
                acc2[c][0] = fma2(w2a[j][0], pack2(nv[j + 1], nv[j + 2]), acc2[c][0]);
                acc2[c][1] = fma2(w2a[j][1], pack2(nv[j + 3], nv[j + 4]), acc2[c][1]);
            }
        }
    }

    float ws[4];
    unpack2(ws2[0], ws[0], ws[1]); unpack2(ws2[1], ws[2], ws[3]);
    float inv[4];
    #pragma unroll
    for (int p = 0; p < 4; ++p) inv[p] = 1.f / ws[p];

    float* ob = out + (long)bz * 3 * HW + ctr;
    #pragma unroll
    for (int c = 0; c < 3; ++c) {
        float a0, a1, a2, a3;
        unpack2(acc2[c][0], a0, a1); unpack2(acc2[c][1], a2, a3);
        float4 o; o.x = a0 * inv[0]; o.y = a1 * inv[1]; o.z = a2 * inv[2]; o.w = a3 * inv[3];
        *(float4*)(ob + c * HW) = o;
    }
}

// ---------------------------------------------------------------------------
// Border ring: 14288 px/batch, bounds-checked; scheduled first so it hides
// under the interior wave.
// ---------------------------------------------------------------------------
__device__ __forceinline__ void border_path(const float* __restrict__ in,
                                            float* __restrict__ out,
                                            int bid, int bz)
{
    const int tid = threadIdx.y * 32 + threadIdx.x;
    int r = bid * 128 + tid;
    if (r >= 14288) return;
    int x, y;
    if (r < 3072)        { y = r >> 10;                x = r & 1023; }
    else if (r < 6144)   { r -= 3072;  y = 1021 + (r >> 10); x = r & 1023; }
    else if (r < 10216)  { r -= 6144;  y = 3 + (r >> 2);     x = r & 3; }
    else                 { r -= 10216; y = 3 + (r >> 2);     x = 1020 + (r & 3); }

    const float* base = in + (long)bz * CIN * HW;
    const long ctr = (long)y * Wd + x;

    float f[8], rp[8];
    #pragma unroll
    for (int c = 0; c < 8; ++c) {
        f[c] = base[c * HW + ctr];
        float pv = base[(8 + c) * HW + ctr];
        rp[c] = -(pv * pv);
    }
    float sv = base[16 * HW + ctr];
    float tv = base[17 * HW + ctr];
    const float sxl = -(sv * sv), syl = -(tv * tv);

    float a0 = 0.f, a1 = 0.f, a2 = 0.f, ws = 0.f;
    for (int i = 0; i < 7; ++i) {
        const int gy = y + i - 3;
        if (gy < 0 || gy >= Hd) continue;
        const float dy2 = (float)((i - 3) * (i - 3));
        for (int j = 0; j < 7; ++j) {
            const int gx = x + j - 3;
            if (gx < 0 || gx >= Wd) continue;
            const float dx2 = (float)((j - 3) * (j - 3));
            const float* q = base + (long)gy * Wd + gx;
            float fn[8];
            float lw = fmaf(sxl, dx2, syl * dy2);
            #pragma unroll
            for (int c = 0; c < 8; ++c) {
                fn[c] = q[c * HW];
                float d = fn[c] - f[c];
                lw = fmaf(rp[c], d * d, lw);
            }
            float w = __expf(lw);
            ws += w;
            a0 = fmaf(w, fn[0], a0);
            a1 = fmaf(w, fn[1], a1);
            a2 = fmaf(w, fn[2], a2);
        }
    }
    float* ob = out + (long)bz * 3 * HW + ctr;
    const float inv = 1.f / ws;
    ob[0]      = a0 * inv;
    ob[HW]     = a1 * inv;
    ob[2 * HW] = a2 * inv;
}

__global__ __launch_bounds__(128, 4)
void bilat_fused(const float* __restrict__ in, float* __restrict__ out)
{
    __shared__ u64 s_rp[16][128];
    __shared__ u64 s_mf[16][128];

    if (blockIdx.y < 14) {
        border_path(in, out, blockIdx.y * 8 + blockIdx.x, blockIdx.z);
    } else {
        interior_path(in, out, s_rp, s_mf, blockIdx.x, blockIdx.y - 14, blockIdx.z);
    }
}

extern "C" void kernel_launch(void* const* d_in, const int* in_sizes, int n_in,
                              void* d_out, int out_size)
{
    const float* in = (const float*)d_in[0];
    float* out = (float*)d_out;

    dim3 blk(32, 4, 1);
    dim3 grd(8, 14 + 255, 2);   // y: 14 border block-rows (112 blocks) + 255 interior
    bilat_fused<<<grd, blk>>>(in, out);
}

// round 5
// speedup vs baseline: 1.3337x; 1.3337x over previous
#include <cuda_runtime.h>

constexpr int Wd = 1024, Hd = 1024;
constexpr long HW = (long)Wd * Hd;
constexpr int CIN = 18;
constexpr float L2E = 1.4426950408889634f;

using u64 = unsigned long long;

__device__ __forceinline__ u64 pack2(float lo, float hi) {
    u64 r; asm("mov.b64 %0,{%1,%2};" : "=l"(r) : "f"(lo), "f"(hi)); return r;
}
__device__ __forceinline__ void unpack2(u64 v, float& lo, float& hi) {
    asm("mov.b64 {%0,%1},%2;" : "=f"(lo), "=f"(hi) : "l"(v));
}
__device__ __forceinline__ u64 fma2(u64 a, u64 b, u64 c) {
    u64 d; asm("fma.rn.f32x2 %0,%1,%2,%3;" : "=l"(d) : "l"(a), "l"(b), "l"(c)); return d;
}
__device__ __forceinline__ u64 add2(u64 a, u64 b) {
    u64 d; asm("add.rn.f32x2 %0,%1,%2;" : "=l"(d) : "l"(a), "l"(b)); return d;
}
__device__ __forceinline__ float ex2(float x) {
    float r; asm("ex2.approx.f32 %0,%1;" : "=f"(r) : "f"(x)); return r;
}
__device__ __forceinline__ u64 bcast2(float x) {
    unsigned u = __float_as_uint(x); return ((u64)u << 32) | u;
}

// ---------------------------------------------------------------------------
// Interior: 4 px/thread, f32x2 math, Horner form, params held in REGISTERS
// (no SMEM round-trip — R3 showed LDS + spills become the binding L1 pipe).
// ---------------------------------------------------------------------------
__device__ __forceinline__ void interior_path(const float* __restrict__ in,
                                              float* __restrict__ out,
                                              int bx, int byi, int bz)
{
    const int gxg = bx * 32 + threadIdx.x;
    const int x0  = 4 + gxg * 4;
    const int y   = 3 + byi * 4 + threadIdx.y;
    if (gxg > 253 || y > 1020) return;

    const float* base = in + (long)bz * CIN * HW;
    const long ctr = (long)y * Wd + x0;

    u64 rp2[8][2], mf2[8][2], K2[2], sxl2[2], syl2[2];
    {
        float Ks[4] = {0.f, 0.f, 0.f, 0.f};
        #pragma unroll
        for (int c = 0; c < 8; ++c) {
            float4 fv = *(const float4*)(base + c * HW + ctr);
            float4 pv = *(const float4*)(base + (8 + c) * HW + ctr);
            const float f4[4] = {fv.x, fv.y, fv.z, fv.w};
            const float p4[4] = {pv.x, pv.y, pv.z, pv.w};
            float rs[4], ms[4];
            #pragma unroll
            for (int p = 0; p < 4; ++p) {
                float r = -(p4[p] * p4[p]) * L2E;        // log2(e) folded in
                rs[p] = r;
                ms[p] = -2.f * r * f4[p];
                Ks[p] = fmaf(r * f4[p], f4[p], Ks[p]);
            }
            rp2[c][0] = pack2(rs[0], rs[1]); rp2[c][1] = pack2(rs[2], rs[3]);
            mf2[c][0] = pack2(ms[0], ms[1]); mf2[c][1] = pack2(ms[2], ms[3]);
        }
        K2[0] = pack2(Ks[0], Ks[1]); K2[1] = pack2(Ks[2], Ks[3]);
        float4 sv = *(const float4*)(base + 16 * HW + ctr);
        float4 tv = *(const float4*)(base + 17 * HW + ctr);
        sxl2[0] = pack2(-(sv.x*sv.x)*L2E, -(sv.y*sv.y)*L2E);
        sxl2[1] = pack2(-(sv.z*sv.z)*L2E, -(sv.w*sv.w)*L2E);
        syl2[0] = pack2(-(tv.x*tv.x)*L2E, -(tv.y*tv.y)*L2E);
        syl2[1] = pack2(-(tv.z*tv.z)*L2E, -(tv.w*tv.w)*L2E);
    }

    u64 acc2[3][2] = {}, ws2[2] = {};

    #pragma unroll 1       // keep body inside I$ L1.5
    for (int i = 0; i < 7; ++i) {
        const int gy = y + i - 3;                        // always in [0,1023]
        const float* rowb = base + (long)gy * Wd + (x0 - 4);
        const u64 dyb = bcast2((float)((i - 3) * (i - 3)));

        u64 s2[7][2];
        {
            const u64 kd0 = fma2(syl2[0], dyb, K2[0]);
            const u64 kd1 = fma2(syl2[1], dyb, K2[1]);
            #pragma unroll
            for (int j = 0; j < 7; ++j) { s2[j][0] = kd0; s2[j][1] = kd1; }
        }

        #pragma unroll
        for (int c = 0; c < 8; ++c) {
            const float* r0 = rowb + c * HW;             // 16B aligned
            float4 v0 = *(const float4*)(r0);
            float4 v1 = *(const float4*)(r0 + 4);
            float4 v2 = *(const float4*)(r0 + 8);
            const float nv[12] = {v0.x, v0.y, v0.z, v0.w,
                                  v1.x, v1.y, v1.z, v1.w,
                                  v2.x, v2.y, v2.z, v2.w};
            #pragma unroll
            for (int j = 0; j < 7; ++j) {
                // pack on the fly: duplicates CSE, avoids a live pv[9] array
                u64 a = pack2(nv[j + 1], nv[j + 2]);
                u64 b = pack2(nv[j + 3], nv[j + 4]);
                // s += fn * (rp*fn + mf)   (Horner: no explicit square)
                s2[j][0] = fma2(a, fma2(rp2[c][0], a, mf2[c][0]), s2[j][0]);
                s2[j][1] = fma2(b, fma2(rp2[c][1], b, mf2[c][1]), s2[j][1]);
            }
        }

        // Weights (s2 dies progressively into w2a)
        u64 w2a[7][2];
        #pragma unroll
        for (int j = 0; j < 7; ++j) {
            const u64 dxb = bcast2((float)((j - 3) * (j - 3)));
            #pragma unroll
            for (int pp = 0; pp < 2; ++pp) {
                u64 lw2 = fma2(sxl2[pp], dxb, s2[j][pp]);
                float a, b; unpack2(lw2, a, b);
                u64 w2 = pack2(ex2(a), ex2(b));
                w2a[j][pp] = w2;
                ws2[pp] = add2(ws2[pp], w2);
            }
        }

        // Accumulate output channels (rows reload as guaranteed L1 hits)
        #pragma unroll
        for (int c = 0; c < 3; ++c) {
            const float* r0 = rowb + c * HW;
            float4 v0 = *(const float4*)(r0);
            float4 v1 = *(const float4*)(r0 + 4);
            float4 v2 = *(const float4*)(r0 + 8);
            const float nv[12] = {v0.x, v0.y, v0.z, v0.w,
                                  v1.x, v1.y, v1.z, v1.w,
                                  v2.x, v2.y, v2.z, v2.w};
            #pragma unroll
            for (int j = 0; j < 7; ++j) {
                acc2[c][0] = fma2(w2a[j][0], pack2(nv[j + 1], nv[j + 2]), acc2[c][0]);
                acc2[c][1] = fma2(w2a[j][1], pack2(nv[j + 3], nv[j + 4]), acc2[c][1]);
            }
        }
    }

    float ws[4];
    unpack2(ws2[0], ws[0], ws[1]); unpack2(ws2[1], ws[2], ws[3]);
    float inv[4];
    #pragma unroll
    for (int p = 0; p < 4; ++p) inv[p] = 1.f / ws[p];

    float* ob = out + (long)bz * 3 * HW + ctr;
    #pragma unroll
    for (int c = 0; c < 3; ++c) {
        float a0, a1, a2, a3;
        unpack2(acc2[c][0], a0, a1); unpack2(acc2[c][1], a2, a3);
        float4 o; o.x = a0 * inv[0]; o.y = a1 * inv[1]; o.z = a2 * inv[2]; o.w = a3 * inv[3];
        *(float4*)(ob + c * HW) = o;
    }
}

// ---------------------------------------------------------------------------
// Border ring: 14288 px/batch, bounds-checked; blocks scheduled first so they
// hide under the interior wave.
// ---------------------------------------------------------------------------
__device__ __forceinline__ void border_path(const float* __restrict__ in,
                                            float* __restrict__ out,
                                            int bid, int bz)
{
    const int tid = threadIdx.y * 32 + threadIdx.x;
    int r = bid * 128 + tid;
    if (r >= 14288) return;
    int x, y;
    if (r < 3072)        { y = r >> 10;                x = r & 1023; }
    else if (r < 6144)   { r -= 3072;  y = 1021 + (r >> 10); x = r & 1023; }
    else if (r < 10216)  { r -= 6144;  y = 3 + (r >> 2);     x = r & 3; }
    else                 { r -= 10216; y = 3 + (r >> 2);     x = 1020 + (r & 3); }

    const float* base = in + (long)bz * CIN * HW;
    const long ctr = (long)y * Wd + x;

    float f[8], rp[8];
    #pragma unroll
    for (int c = 0; c < 8; ++c) {
        f[c] = base[c * HW + ctr];
        float pv = base[(8 + c) * HW + ctr];
        rp[c] = -(pv * pv);
    }
    float sv = base[16 * HW + ctr];
    float tv = base[17 * HW + ctr];
    const float sxl = -(sv * sv), syl = -(tv * tv);

    float a0 = 0.f, a1 = 0.f, a2 = 0.f, ws = 0.f;
    for (int i = 0; i < 7; ++i) {
        const int gy = y + i - 3;
        if (gy < 0 || gy >= Hd) continue;
        const float dy2 = (float)((i - 3) * (i - 3));
        for (int j = 0; j < 7; ++j) {
            const int gx = x + j - 3;
            if (gx < 0 || gx >= Wd) continue;
            const float dx2 = (float)((j - 3) * (j - 3));
            const float* q = base + (long)gy * Wd + gx;
            float fn[8];
            float lw = fmaf(sxl, dx2, syl * dy2);
            #pragma unroll
            for (int c = 0; c < 8; ++c) {
                fn[c] = q[c * HW];
                float d = fn[c] - f[c];
                lw = fmaf(rp[c], d * d, lw);
            }
            float w = __expf(lw);
            ws += w;
            a0 = fmaf(w, fn[0], a0);
            a1 = fmaf(w, fn[1], a1);
            a2 = fmaf(w, fn[2], a2);
        }
    }
    float* ob = out + (long)bz * 3 * HW + ctr;
    const float inv = 1.f / ws;
    ob[0]      = a0 * inv;
    ob[HW]     = a1 * inv;
    ob[2 * HW] = a2 * inv;
}

__global__ __launch_bounds__(128, 3)
void bilat_fused(const float* __restrict__ in, float* __restrict__ out)
{
    if (blockIdx.y < 14) {
        border_path(in, out, blockIdx.y * 8 + blockIdx.x, blockIdx.z);
    } else {
        interior_path(in, out, blockIdx.x, blockIdx.y - 14, blockIdx.z);
    }
}

extern "C" void kernel_launch(void* const* d_in, const int* in_sizes, int n_in,
                              void* d_out, int out_size)
{
    const float* in = (const float*)d_in[0];
    float* out = (float*)d_out;

    dim3 blk(32, 4, 1);
    dim3 grd(8, 14 + 255, 2);   // 112 border blocks first, then 255x8 interior
    bilat_fused<<<grd, blk>>>(in, out);
}

// round 6
// speedup vs baseline: 1.3490x; 1.0115x over previous
#include <cuda_runtime.h>

constexpr int Wd = 1024, Hd = 1024;
constexpr long HW = (long)Wd * Hd;
constexpr int CIN = 18;
constexpr float L2E = 1.4426950408889634f;

// Tile: 8 channels x 10 rows x 136 cols (float) = 43,520 B static smem.
constexpr int TP = 136;             // tile pitch (floats)
constexpr int TROW = 10;            // rows per tile (4 output + 6 halo)
constexpr int TCH = TROW * TP;      // floats per channel = 1360

using u64 = unsigned long long;

__device__ __forceinline__ u64 pack2(float lo, float hi) {
    u64 r; asm("mov.b64 %0,{%1,%2};" : "=l"(r) : "f"(lo), "f"(hi)); return r;
}
__device__ __forceinline__ void unpack2(u64 v, float& lo, float& hi) {
    asm("mov.b64 {%0,%1},%2;" : "=f"(lo), "=f"(hi) : "l"(v));
}
__device__ __forceinline__ u64 fma2(u64 a, u64 b, u64 c) {
    u64 d; asm("fma.rn.f32x2 %0,%1,%2,%3;" : "=l"(d) : "l"(a), "l"(b), "l"(c)); return d;
}
__device__ __forceinline__ u64 add2(u64 a, u64 b) {
    u64 d; asm("add.rn.f32x2 %0,%1,%2;" : "=l"(d) : "l"(a), "l"(b)); return d;
}
__device__ __forceinline__ float ex2(float x) {
    float r; asm("ex2.approx.f32 %0,%1;" : "=f"(r) : "f"(x)); return r;
}
__device__ __forceinline__ u64 bcast2(float x) {
    unsigned u = __float_as_uint(x); return ((u64)u << 32) | u;
}

// ---------------------------------------------------------------------------
// Interior: block = 32 x-groups (4 px each) x 4 y-rows. Input halo staged to
// smem once; main loop is pure LDS + f32x2 FFMA (Horner) + ex2.
// ---------------------------------------------------------------------------
__device__ __forceinline__ void interior_path(const float* __restrict__ in,
                                              float* __restrict__ out,
                                              float* __restrict__ tile,
                                              int bx, int byi, int bz)
{
    const int g   = threadIdx.x;                     // 0..31 x-group in block
    const int ty  = threadIdx.y;                     // 0..3
    const int tid = ty * 32 + g;
    const int gxg = bx * 32 + g;
    const int x0  = 4 + gxg * 4;
    const int y   = 3 + byi * 4 + ty;

    const float* base = in + (long)bz * CIN * HW;

    // ---- Stage the 8 filterable channels' halo rows into smem (all threads) ----
    {
        const int tx0 = bx * 128;                    // tile col 0 in global x
        const int gy0 = byi * 4;                     // tile row 0 in global y
        // 8ch * 10 rows * 34 float4 = 2720 float4
        for (int idx = tid; idx < 2720; idx += 128) {
            const int row = idx / 34;                // 0..79
            const int k   = idx - row * 34;          // 0..33
            const int c   = row / TROW;
            const int r   = row - c * TROW;
            const int gx  = tx0 + k * 4;
            const int gy  = gy0 + r;
            if (gx <= 1020 && gy <= 1023) {
                float4 v = *(const float4*)(base + c * HW + (long)gy * Wd + gx);
                *(float4*)(tile + c * TCH + r * TP + k * 4) = v;
            }
        }
    }
    __syncthreads();
    if (gxg > 253 || y > 1020) return;

    const long ctr = (long)y * Wd + x0;

    u64 rp2[8][2], mf2[8][2], K2[2], sxl2[2], syl2[2];
    {
        float Ks[4] = {0.f, 0.f, 0.f, 0.f};
        #pragma unroll
        for (int c = 0; c < 8; ++c) {
            // center values from the tile (already staged; cols g*4+4..+7)
            float4 fv = *(const float4*)(tile + c * TCH + (ty + 3) * TP + g * 4 + 4);
            float4 pv = *(const float4*)(base + (8 + c) * HW + ctr);
            const float f4[4] = {fv.x, fv.y, fv.z, fv.w};
            const float p4[4] = {pv.x, pv.y, pv.z, pv.w};
            float rs[4], ms[4];
            #pragma unroll
            for (int p = 0; p < 4; ++p) {
                float r = -(p4[p] * p4[p]) * L2E;    // log2(e) folded in
                rs[p] = r;
                ms[p] = -2.f * r * f4[p];
                Ks[p] = fmaf(r * f4[p], f4[p], Ks[p]);
            }
            rp2[c][0] = pack2(rs[0], rs[1]); rp2[c][1] = pack2(rs[2], rs[3]);
            mf2[c][0] = pack2(ms[0], ms[1]); mf2[c][1] = pack2(ms[2], ms[3]);
        }
        K2[0] = pack2(Ks[0], Ks[1]); K2[1] = pack2(Ks[2], Ks[3]);
        float4 sv = *(const float4*)(base + 16 * HW + ctr);
        float4 tv = *(const float4*)(base + 17 * HW + ctr);
        sxl2[0] = pack2(-(sv.x*sv.x)*L2E, -(sv.y*sv.y)*L2E);
        sxl2[1] = pack2(-(sv.z*sv.z)*L2E, -(sv.w*sv.w)*L2E);
        syl2[0] = pack2(-(tv.x*tv.x)*L2E, -(tv.y*tv.y)*L2E);
        syl2[1] = pack2(-(tv.z*tv.z)*L2E, -(tv.w*tv.w)*L2E);
    }

    u64 acc2[3][2] = {}, ws2[2] = {};

    #pragma unroll 1       // keep body inside I$ L1.5
    for (int i = 0; i < 7; ++i) {
        // this thread's neighbor row in the tile
        const float* rowp = tile + (ty + i) * TP + g * 4;
        const u64 dyb = bcast2((float)((i - 3) * (i - 3)));

        u64 s2[7][2];
        {
            const u64 kd0 = fma2(syl2[0], dyb, K2[0]);
            const u64 kd1 = fma2(syl2[1], dyb, K2[1]);
            #pragma unroll
            for (int j = 0; j < 7; ++j) { s2[j][0] = kd0; s2[j][1] = kd1; }
        }

        #pragma unroll
        for (int c = 0; c < 8; ++c) {
            const float* r0 = rowp + c * TCH;        // c*TCH folds to LDS imm
            float4 v0 = *(const float4*)(r0);
            float4 v1 = *(const float4*)(r0 + 4);
            float4 v2 = *(const float4*)(r0 + 8);
            const float nv[12] = {v0.x, v0.y, v0.z, v0.w,
                                  v1.x, v1.y, v1.z, v1.w,
                                  v2.x, v2.y, v2.z, v2.w};
            #pragma unroll
            for (int j = 0; j < 7; ++j) {
                u64 a = pack2(nv[j + 1], nv[j + 2]);
                u64 b = pack2(nv[j + 3], nv[j + 4]);
                // s += fn * (rp*fn + mf)   (Horner)
                s2[j][0] = fma2(a, fma2(rp2[c][0], a, mf2[c][0]), s2[j][0]);
                s2[j][1] = fma2(b, fma2(rp2[c][1], b, mf2[c][1]), s2[j][1]);
            }
        }

        // Weights
        u64 w2a[7][2];
        #pragma unroll
        for (int j = 0; j < 7; ++j) {
            const u64 dxb = bcast2((float)((j - 3) * (j - 3)));
            #pragma unroll
            for (int pp = 0; pp < 2; ++pp) {
                u64 lw2 = fma2(sxl2[pp], dxb, s2[j][pp]);
                float a, b; unpack2(lw2, a, b);
                u64 w2 = pack2(ex2(a), ex2(b));
                w2a[j][pp] = w2;
                ws2[pp] = add2(ws2[pp], w2);
            }
        }

        // Accumulate output channels (rows re-read from smem: 29-cyc LDS)
        #pragma unroll
        for (int c = 0; c < 3; ++c) {
            const float* r0 = rowp + c * TCH;
            float4 v0 = *(const float4*)(r0);
            float4 v1 = *(const float4*)(r0 + 4);
            float4 v2 = *(const float4*)(r0 + 8);
            const float nv[12] = {v0.x, v0.y, v0.z, v0.w,
                                  v1.x, v1.y, v1.z, v1.w,
                                  v2.x, v2.y, v2.z, v2.w};
            #pragma unroll
            for (int j = 0; j < 7; ++j) {
                acc2[c][0] = fma2(w2a[j][0], pack2(nv[j + 1], nv[j + 2]), acc2[c][0]);
                acc2[c][1] = fma2(w2a[j][1], pack2(nv[j + 3], nv[j + 4]), acc2[c][1]);
            }
        }
    }

    float ws[4];
    unpack2(ws2[0], ws[0], ws[1]); unpack2(ws2[1], ws[2], ws[3]);
    float inv[4];
    #pragma unroll
    for (int p = 0; p < 4; ++p) inv[p] = 1.f / ws[p];

    float* ob = out + (long)bz * 3 * HW + ctr;
    #pragma unroll
    for (int c = 0; c < 3; ++c) {
        float a0, a1, a2, a3;
        unpack2(acc2[c][0], a0, a1); unpack2(acc2[c][1], a2, a3);
        float4 o; o.x = a0 * inv[0]; o.y = a1 * inv[1]; o.z = a2 * inv[2]; o.w = a3 * inv[3];
        *(float4*)(ob + c * HW) = o;
    }
}

// ---------------------------------------------------------------------------
// Border ring: 14288 px/batch, bounds-checked; blocks scheduled first so they
// hide under the interior wave.
// ---------------------------------------------------------------------------
__device__ __forceinline__ void border_path(const float* __restrict__ in,
                                            float* __restrict__ out,
                                            int bid, int bz)
{
    const int tid = threadIdx.y * 32 + threadIdx.x;
    int r = bid * 128 + tid;
    if (r >= 14288) return;
    int x, y;
    if (r < 3072)        { y = r >> 10;                x = r & 1023; }
    else if (r < 6144)   { r -= 3072;  y = 1021 + (r >> 10); x = r & 1023; }
    else if (r < 10216)  { r -= 6144;  y = 3 + (r >> 2);     x = r & 3; }
    else                 { r -= 10216; y = 3 + (r >> 2);     x = 1020 + (r & 3); }

    const float* base = in + (long)bz * CIN * HW;
    const long ctr = (long)y * Wd + x;

    float f[8], rp[8];
    #pragma unroll
    for (int c = 0; c < 8; ++c) {
        f[c] = base[c * HW + ctr];
        float pv = base[(8 + c) * HW + ctr];
        rp[c] = -(pv * pv);
    }
    float sv = base[16 * HW + ctr];
    float tv = base[17 * HW + ctr];
    const float sxl = -(sv * sv), syl = -(tv * tv);

    float a0 = 0.f, a1 = 0.f, a2 = 0.f, ws = 0.f;
    for (int i = 0; i < 7; ++i) {
        const int gy = y + i - 3;
        if (gy < 0 || gy >= Hd) continue;
        const float dy2 = (float)((i - 3) * (i - 3));
        for (int j = 0; j < 7; ++j) {
            const int gx = x + j - 3;
            if (gx < 0 || gx >= Wd) continue;
            const float dx2 = (float)((j - 3) * (j - 3));
            const float* q = base + (long)gy * Wd + gx;
            float fn[8];
            float lw = fmaf(sxl, dx2, syl * dy2);
            #pragma unroll
            for (int c = 0; c < 8; ++c) {
                fn[c] = q[c * HW];
                float d = fn[c] - f[c];
                lw = fmaf(rp[c], d * d, lw);
            }
            float w = __expf(lw);
            ws += w;
            a0 = fmaf(w, fn[0], a0);
            a1 = fmaf(w, fn[1], a1);
            a2 = fmaf(w, fn[2], a2);
        }
    }
    float* ob = out + (long)bz * 3 * HW + ctr;
    const float inv = 1.f / ws;
    ob[0]      = a0 * inv;
    ob[HW]     = a1 * inv;
    ob[2 * HW] = a2 * inv;
}

__global__ __launch_bounds__(128, 3)
void bilat_fused(const float* __restrict__ in, float* __restrict__ out)
{
    __shared__ __align__(16) float tile[8 * TCH];    // 43,520 B

    if (blockIdx.y < 14) {
        border_path(in, out, blockIdx.y * 8 + blockIdx.x, blockIdx.z);
    } else {
        interior_path(in, out, tile, blockIdx.x, blockIdx.y - 14, blockIdx.z);
    }
}

extern "C" void kernel_launch(void* const* d_in, const int* in_sizes, int n_in,
                              void* d_out, int out_size)
{
    const float* in = (const float*)d_in[0];
    float* out = (float*)d_out;

    dim3 blk(32, 4, 1);
    dim3 grd(8, 14 + 255, 2);   // 112 border blocks first, then 255x8 interior
    bilat_fused<<<grd, blk>>>(in, out);
}